// round 10
// baseline (speedup 1.0000x reference)
#include <cuda_runtime.h>
#include <cuda_fp16.h>
#include <cstdint>

// Y = X @ (W_nf4 * c1 * c_kbit_2) + (X@L1)@L2  ==  X @ (W' )  with
//   W' = W_nf4*c1*c_kbit_2 + L1@L2   (rank-16 update folded into the weight)
// R9->R10: move the LoRA fold from the X side (8192 rows, issue-bound 70us)
// into pack_w (4096 rows, DRAM-bound, idle fma pipe). pack_x becomes a pure
// fp32->fp16 convert; K = 4096 exactly (no appended columns, 64 k-tiles).
//   Xe fp16 [8192,4096] = fp16(X)
//   We fp16 [4096,4096] = fp16(W^T + (L1@L2)^T)   (K contiguous per N row)
// GEMM via mma.sync.m16n8k16 (tcgen05 rejected at plain sm_103 PTX target);
// loop is the proven R6/R8 cross-iteration-prefetch pipeline.

static constexpr int D_IN  = 4096;
static constexpr int D_OUT = 4096;
static constexpr int NROWS = 8192;
static constexpr int KPAD  = 4096;

static constexpr int BM = 128, BN = 128, BK = 64, S = 3;
static constexpr int KT = KPAD / BK;              // 64
static constexpr int ABYTES = BM * BK * 2;        // 16384
static constexpr int BBYTES = BN * BK * 2;        // 16384
static constexpr int STAGE  = ABYTES + BBYTES;    // 32768
static constexpr int SMEM_SZ = S * STAGE;         // 98304 (2 CTAs/SM)

__device__ __align__(16) __half g_Xe[(size_t)NROWS * KPAD];   // 64 MB
__device__ __align__(16) __half g_We[(size_t)D_OUT * KPAD];   // 32 MB

// ------------------------------ PTX helpers -------------------------------
__device__ __forceinline__ void cp16(uint32_t dst, const void* src) {
    asm volatile("cp.async.cg.shared.global [%0], [%1], 16;"
                 :: "r"(dst), "l"(__cvta_generic_to_global(src)) : "memory");
}
#define CP_COMMIT() asm volatile("cp.async.commit_group;" ::: "memory")
#define CP_WAIT(n)  asm volatile("cp.async.wait_group %0;" :: "n"(n) : "memory")

#define LDSM4(r, a) \
    asm volatile("ldmatrix.sync.aligned.m8n8.x4.shared.b16 {%0,%1,%2,%3}, [%4];" \
        : "=r"((r)[0]), "=r"((r)[1]), "=r"((r)[2]), "=r"((r)[3]) : "r"(a))

#define MMA16816(d, a, b) \
    asm volatile("mma.sync.aligned.m16n8k16.row.col.f32.f16.f16.f32 " \
        "{%0,%1,%2,%3}, {%4,%5,%6,%7}, {%8,%9}, {%0,%1,%2,%3};" \
        : "+f"((d)[0]), "+f"((d)[1]), "+f"((d)[2]), "+f"((d)[3]) \
        : "r"((a)[0]), "r"((a)[1]), "r"((a)[2]), "r"((a)[3]), \
          "r"((b)[0]), "r"((b)[1]))

__device__ __forceinline__ uint32_t swz(uint32_t o) { return o ^ ((o >> 3) & 0x70); }

// ------------------- pack_X: pure fp32 -> fp16 convert ---------------------
// One float4 (4 elems) per thread: 128-bit load, 64-bit store, fully coalesced.
__global__ void __launch_bounds__(256)
pack_x_kernel(const float* __restrict__ X) {
    size_t idx = ((size_t)blockIdx.x * 256 + threadIdx.x) * 4;
    float4 v = *(const float4*)(X + idx);
    __half2 h0 = __floats2half2_rn(v.x, v.y);
    __half2 h1 = __floats2half2_rn(v.z, v.w);
    *(__half2*)(g_Xe + idx)     = h0;
    *(__half2*)(g_Xe + idx + 2) = h1;
}

// -------- pack_W: dequant + rank-16 LoRA add + transpose to We -------------
// Block = 64x64 tile of W. tile[k][n] = Wq*c1*ck; write We[n][k] =
// fp16(tile + sum_j L1[k][j]*L2[j][n]). L1 row kept in regs (cidx fixed per
// thread); L2 16x64 tile in smem, warp-broadcast reads.
__global__ void __launch_bounds__(256)
pack_w_kernel(const float* __restrict__ Wq, const float* __restrict__ c1p,
              const float* __restrict__ ck, const float* __restrict__ L1,
              const float* __restrict__ L2) {
    __shared__ float tile[64 * 65];      // dequantized W tile (k-major)
    __shared__ float sL2[16][68];        // L2[j][n0+n]
    const float c1 = *c1p;
    const int tid = threadIdx.x;
    const int n0 = blockIdx.x * 64, k0 = blockIdx.y * 64;
    const int cidx = tid & 63, ridx = tid >> 6;

    // dequant into smem (transposed access pattern later)
#pragma unroll
    for (int ro = 0; ro < 16; ro++) {
        int kk = ro * 4 + ridx;
        size_t g = (size_t)(k0 + kk) * D_OUT + n0 + cidx;
        tile[kk * 65 + cidx] = Wq[g] * c1 * ck[g];
    }

    // L2 tile: 16 rows x 64 cols = 1024 floats, 4 per thread
    {
        int i = tid * 4;                 // 0..1023, row = i>>6, col = i&63
        int j = i >> 6, c = i & 63;
        float4 v = *(const float4*)(L2 + (size_t)j * D_OUT + n0 + c);
        sL2[j][c] = v.x; sL2[j][c + 1] = v.y;
        sL2[j][c + 2] = v.z; sL2[j][c + 3] = v.w;
    }

    // L1 row for this thread's k (= k0 + cidx): 16 consecutive floats
    float l1r[16];
    {
        const float4* lp = (const float4*)(L1 + (size_t)(k0 + cidx) * 16);
#pragma unroll
        for (int q = 0; q < 4; q++) {
            float4 v = lp[q];
            l1r[q * 4] = v.x; l1r[q * 4 + 1] = v.y;
            l1r[q * 4 + 2] = v.z; l1r[q * 4 + 3] = v.w;
        }
    }
    __syncthreads();

#pragma unroll
    for (int ro = 0; ro < 16; ro++) {
        int nn = ro * 4 + ridx;          // same nn across each warp -> broadcast
        float acc = tile[cidx * 65 + nn];
#pragma unroll
        for (int j = 0; j < 16; j++)
            acc += l1r[j] * sL2[j][nn];
        g_We[(size_t)(n0 + nn) * KPAD + k0 + cidx] = __float2half_rn(acc);
    }
}

// ------------------------------ GEMM kernel --------------------------------
// Exact R6/R8 loop: 4 warps (2x2), warp tile 64x64, cross-iteration frag
// prefetch with deferred commit_group; sync -> load_frag(1) -> mma(0).
__global__ void __launch_bounds__(128, 2)
gemm_kernel(float* __restrict__ Y) {
    extern __shared__ char smem[];
    const uint32_t sb = (uint32_t)__cvta_generic_to_shared(smem);
    const int tid = threadIdx.x, wid = tid >> 5, lane = tid & 31;
    const int m0 = blockIdx.y * BM, n0 = blockIdx.x * BN;
    const int wm = wid & 1, wn = wid >> 1;
    const int gid = lane >> 2, tig = lane & 3;

    auto loadA = [&](int kt, int slot) {
        const __half* src = g_Xe + (size_t)m0 * KPAD + (size_t)kt * BK;
        uint32_t base = sb + slot * STAGE;
#pragma unroll
        for (int i = 0; i < 8; i++) {
            int idx = tid + i * 128;
            int r = idx >> 3, c = idx & 7;
            cp16(base + swz((uint32_t)(r * 128 + c * 16)),
                 src + (size_t)r * KPAD + c * 8);
        }
    };
    auto loadB = [&](int kt, int slot) {
        const __half* src = g_We + (size_t)n0 * KPAD + (size_t)kt * BK;
        uint32_t base = sb + slot * STAGE + ABYTES;
#pragma unroll
        for (int i = 0; i < 8; i++) {
            int idx = tid + i * 128;
            int r = idx >> 3, c = idx & 7;
            cp16(base + swz((uint32_t)(r * 128 + c * 16)),
                 src + (size_t)r * KPAD + c * 8);
        }
    };

    float acc[4][8][4];
#pragma unroll
    for (int t = 0; t < 4; t++)
#pragma unroll
        for (int n = 0; n < 8; n++)
#pragma unroll
            for (int j = 0; j < 4; j++) acc[t][n][j] = 0.f;

#pragma unroll
    for (int s = 0; s < S - 1; s++) { loadA(s, s); loadB(s, s); CP_COMMIT(); }

    const uint32_t a_row = (uint32_t)(wm * 64 + (lane & 15));
    const uint32_t a_chk = (uint32_t)(lane >> 4);
    const uint32_t b_row = (uint32_t)(wn * 64 + ((lane >> 4) & 1) * 8 + (lane & 7));
    const uint32_t b_chk = (uint32_t)((lane >> 3) & 1);

    uint32_t af[2][4][4];
    uint32_t bf[2][8][2];

    auto load_frag = [&](int buf, uint32_t abase, int ks) {
        const uint32_t bbase = abase + ABYTES;
#pragma unroll
        for (int t = 0; t < 4; t++) {
            uint32_t off = (a_row + t * 16) * 128 + (a_chk + ks * 2) * 16;
            LDSM4(af[buf][t], abase + swz(off));
        }
#pragma unroll
        for (int g = 0; g < 4; g++) {
            uint32_t off = (b_row + g * 16) * 128 + (b_chk + ks * 2) * 16;
            uint32_t r[4];
            LDSM4(r, bbase + swz(off));
            bf[buf][2 * g][0] = r[0];     bf[buf][2 * g][1] = r[1];
            bf[buf][2 * g + 1][0] = r[2]; bf[buf][2 * g + 1][1] = r[3];
        }
    };
    auto mma_block = [&](int buf) {
#pragma unroll
        for (int t = 0; t < 4; t++)
#pragma unroll
            for (int n = 0; n < 8; n++)
                MMA16816(acc[t][n], af[buf][t], bf[buf][n]);
    };

    // Wait stage 0 (leave stage 1 in flight), prefetch its ks=0 fragments.
    CP_WAIT(1);
    __syncthreads();
    load_frag(0, sb + 0 * STAGE, 0);

    for (int kt = 0; kt < KT; kt++) {
        const uint32_t abase = sb + (kt % S) * STAGE;
        // Barrier: about to overwrite slot (kt+2)%S == (kt-1)%S. All reads of
        // stage kt-1 (and the prefetch read of stage kt) happened before here.
        __syncthreads();

        load_frag(1, abase, 1);          // ks=1 frags first (critical path)
        mma_block(0);                    // ks=0 (prefetched)

        if (kt + 2 < KT) {               // issue next stage UNCOMMITTED
            loadA(kt + 2, (kt + 2) % S);
            loadB(kt + 2, (kt + 2) % S);
        }

        load_frag(0, abase, 2);
        mma_block(1);                    // ks=1

        load_frag(1, abase, 3);
        mma_block(0);                    // ks=2

        if (kt + 1 < KT) {
            CP_WAIT(0);                  // drains stage kt+1 only (kt+2 uncommitted)
            load_frag(0, sb + ((kt + 1) % S) * STAGE, 0);   // prefetch next ks=0
        }
        mma_block(1);                    // ks=3
        CP_COMMIT();                     // name stage kt+2's group
    }

    // Epilogue: direct float2 stores
#pragma unroll
    for (int t = 0; t < 4; t++) {
        const int r0 = m0 + wm * 64 + t * 16 + gid;
        float* y0 = Y + (size_t)r0 * D_OUT + n0 + wn * 64 + tig * 2;
        float* y1 = y0 + (size_t)8 * D_OUT;
#pragma unroll
        for (int n = 0; n < 8; n++) {
            *(float2*)(y0 + n * 8) = make_float2(acc[t][n][0], acc[t][n][1]);
            *(float2*)(y1 + n * 8) = make_float2(acc[t][n][2], acc[t][n][3]);
        }
    }
}

// ------------------------------- launcher ----------------------------------
extern "C" void kernel_launch(void* const* d_in, const int* in_sizes, int n_in,
                              void* d_out, int out_size) {
    const float* X  = (const float*)d_in[0];
    const float* Wq = (const float*)d_in[1];
    const float* c1 = (const float*)d_in[2];
    const float* ck = (const float*)d_in[3];
    const float* L1 = (const float*)d_in[4];
    const float* L2 = (const float*)d_in[5];
    float* Y = (float*)d_out;

    cudaFuncSetAttribute(gemm_kernel, cudaFuncAttributeMaxDynamicSharedMemorySize, SMEM_SZ);

    pack_x_kernel<<<(NROWS * D_IN / 4) / 256, 256>>>(X);
    pack_w_kernel<<<dim3(D_OUT / 64, D_IN / 64), 256>>>(Wq, c1, ck, L1, L2);
    gemm_kernel<<<dim3(D_OUT / BN, NROWS / BM), 128, SMEM_SZ>>>(Y);
}

// round 11
// speedup vs baseline: 1.0223x; 1.0223x over previous
#include <cuda_runtime.h>
#include <cuda_fp16.h>
#include <cstdint>

// Y = X @ (W_nf4 * c1 * c_kbit_2) + (X@L1)@L2  ==  X @ W'  with
//   W' = W_nf4*c1*c_kbit_2 + L1@L2   (rank-16 update folded into the weight)
// R10->R11: R10's KPAD=4096 made row stride a power of two (8192B) which
// degenerates the L2 addr->slice hash (bits {8,10-27}) => cp.async bursts
// camped on few LTS slices and GEMM regressed ~40us. Restore a non-pow2
// stride: KPAD=4128 (8256B). GEMM still loops KT=64 over K=4096; the 32 pad
// columns are never read. LoRA fold stays in pack_w (R10's win).
//   Xe fp16 [8192,4128] (cols 0..4095 = fp16(X))
//   We fp16 [4096,4128] (cols 0..4095 = fp16(W^T + (L1@L2)^T))

static constexpr int D_IN  = 4096;
static constexpr int D_OUT = 4096;
static constexpr int NROWS = 8192;
static constexpr int KPAD  = 4128;    // non-pow2 row stride (8256 B)

static constexpr int BM = 128, BN = 128, BK = 64, S = 3;
static constexpr int KT = D_IN / BK;              // 64
static constexpr int ABYTES = BM * BK * 2;        // 16384
static constexpr int BBYTES = BN * BK * 2;        // 16384
static constexpr int STAGE  = ABYTES + BBYTES;    // 32768
static constexpr int SMEM_SZ = S * STAGE;         // 98304 (2 CTAs/SM)

__device__ __align__(16) __half g_Xe[(size_t)NROWS * KPAD];   // ~64.5 MB
__device__ __align__(16) __half g_We[(size_t)D_OUT * KPAD];   // ~32.3 MB

// ------------------------------ PTX helpers -------------------------------
__device__ __forceinline__ void cp16(uint32_t dst, const void* src) {
    asm volatile("cp.async.cg.shared.global [%0], [%1], 16;"
                 :: "r"(dst), "l"(__cvta_generic_to_global(src)) : "memory");
}
#define CP_COMMIT() asm volatile("cp.async.commit_group;" ::: "memory")
#define CP_WAIT(n)  asm volatile("cp.async.wait_group %0;" :: "n"(n) : "memory")

#define LDSM4(r, a) \
    asm volatile("ldmatrix.sync.aligned.m8n8.x4.shared.b16 {%0,%1,%2,%3}, [%4];" \
        : "=r"((r)[0]), "=r"((r)[1]), "=r"((r)[2]), "=r"((r)[3]) : "r"(a))

#define MMA16816(d, a, b) \
    asm volatile("mma.sync.aligned.m16n8k16.row.col.f32.f16.f16.f32 " \
        "{%0,%1,%2,%3}, {%4,%5,%6,%7}, {%8,%9}, {%0,%1,%2,%3};" \
        : "+f"((d)[0]), "+f"((d)[1]), "+f"((d)[2]), "+f"((d)[3]) \
        : "r"((a)[0]), "r"((a)[1]), "r"((a)[2]), "r"((a)[3]), \
          "r"((b)[0]), "r"((b)[1]))

__device__ __forceinline__ uint32_t swz(uint32_t o) { return o ^ ((o >> 3) & 0x70); }

// ------------------- pack_X: fp32 -> fp16 convert (padded rows) ------------
// 4 elems/thread, row-aware so the 32 pad cols are skipped. Loads/stores stay
// fully coalesced (1024 elems per block divides the 4096-col rows).
__global__ void __launch_bounds__(256)
pack_x_kernel(const float* __restrict__ X) {
    size_t e = ((size_t)blockIdx.x * 256 + threadIdx.x) * 4;   // index into X
    size_t row = e >> 12, col = e & 4095;
    float4 v = *(const float4*)(X + e);
    __half* dst = g_Xe + row * KPAD + col;
    *(__half2*)(dst)     = __floats2half2_rn(v.x, v.y);
    *(__half2*)(dst + 2) = __floats2half2_rn(v.z, v.w);
}

// -------- pack_W: dequant + rank-16 LoRA add + transpose to We -------------
__global__ void __launch_bounds__(256)
pack_w_kernel(const float* __restrict__ Wq, const float* __restrict__ c1p,
              const float* __restrict__ ck, const float* __restrict__ L1,
              const float* __restrict__ L2) {
    __shared__ float tile[64 * 65];      // dequantized W tile (k-major)
    __shared__ float sL2[16][68];        // L2[j][n0+n]
    const float c1 = *c1p;
    const int tid = threadIdx.x;
    const int n0 = blockIdx.x * 64, k0 = blockIdx.y * 64;
    const int cidx = tid & 63, ridx = tid >> 6;

#pragma unroll
    for (int ro = 0; ro < 16; ro++) {
        int kk = ro * 4 + ridx;
        size_t g = (size_t)(k0 + kk) * D_OUT + n0 + cidx;
        tile[kk * 65 + cidx] = Wq[g] * c1 * ck[g];
    }

    {   // L2 tile: 16 rows x 64 cols, 4 per thread
        int i = tid * 4;
        int j = i >> 6, c = i & 63;
        float4 v = *(const float4*)(L2 + (size_t)j * D_OUT + n0 + c);
        sL2[j][c] = v.x; sL2[j][c + 1] = v.y;
        sL2[j][c + 2] = v.z; sL2[j][c + 3] = v.w;
    }

    float l1r[16];                       // L1 row for k = k0 + cidx
    {
        const float4* lp = (const float4*)(L1 + (size_t)(k0 + cidx) * 16);
#pragma unroll
        for (int q = 0; q < 4; q++) {
            float4 v = lp[q];
            l1r[q * 4] = v.x; l1r[q * 4 + 1] = v.y;
            l1r[q * 4 + 2] = v.z; l1r[q * 4 + 3] = v.w;
        }
    }
    __syncthreads();

#pragma unroll
    for (int ro = 0; ro < 16; ro++) {
        int nn = ro * 4 + ridx;          // same nn across each warp -> broadcast
        float acc = tile[cidx * 65 + nn];
#pragma unroll
        for (int j = 0; j < 16; j++)
            acc += l1r[j] * sL2[j][nn];
        g_We[(size_t)(n0 + nn) * KPAD + k0 + cidx] = __float2half_rn(acc);
    }
}

// ------------------------------ GEMM kernel --------------------------------
// Exact R6/R8 loop: 4 warps (2x2), warp tile 64x64, cross-iteration frag
// prefetch with deferred commit_group; sync -> load_frag(1) -> mma(0).
__global__ void __launch_bounds__(128, 2)
gemm_kernel(float* __restrict__ Y) {
    extern __shared__ char smem[];
    const uint32_t sb = (uint32_t)__cvta_generic_to_shared(smem);
    const int tid = threadIdx.x, wid = tid >> 5, lane = tid & 31;
    const int m0 = blockIdx.y * BM, n0 = blockIdx.x * BN;
    const int wm = wid & 1, wn = wid >> 1;
    const int gid = lane >> 2, tig = lane & 3;

    auto loadA = [&](int kt, int slot) {
        const __half* src = g_Xe + (size_t)m0 * KPAD + (size_t)kt * BK;
        uint32_t base = sb + slot * STAGE;
#pragma unroll
        for (int i = 0; i < 8; i++) {
            int idx = tid + i * 128;
            int r = idx >> 3, c = idx & 7;
            cp16(base + swz((uint32_t)(r * 128 + c * 16)),
                 src + (size_t)r * KPAD + c * 8);
        }
    };
    auto loadB = [&](int kt, int slot) {
        const __half* src = g_We + (size_t)n0 * KPAD + (size_t)kt * BK;
        uint32_t base = sb + slot * STAGE + ABYTES;
#pragma unroll
        for (int i = 0; i < 8; i++) {
            int idx = tid + i * 128;
            int r = idx >> 3, c = idx & 7;
            cp16(base + swz((uint32_t)(r * 128 + c * 16)),
                 src + (size_t)r * KPAD + c * 8);
        }
    };

    float acc[4][8][4];
#pragma unroll
    for (int t = 0; t < 4; t++)
#pragma unroll
        for (int n = 0; n < 8; n++)
#pragma unroll
            for (int j = 0; j < 4; j++) acc[t][n][j] = 0.f;

#pragma unroll
    for (int s = 0; s < S - 1; s++) { loadA(s, s); loadB(s, s); CP_COMMIT(); }

    const uint32_t a_row = (uint32_t)(wm * 64 + (lane & 15));
    const uint32_t a_chk = (uint32_t)(lane >> 4);
    const uint32_t b_row = (uint32_t)(wn * 64 + ((lane >> 4) & 1) * 8 + (lane & 7));
    const uint32_t b_chk = (uint32_t)((lane >> 3) & 1);

    uint32_t af[2][4][4];
    uint32_t bf[2][8][2];

    auto load_frag = [&](int buf, uint32_t abase, int ks) {
        const uint32_t bbase = abase + ABYTES;
#pragma unroll
        for (int t = 0; t < 4; t++) {
            uint32_t off = (a_row + t * 16) * 128 + (a_chk + ks * 2) * 16;
            LDSM4(af[buf][t], abase + swz(off));
        }
#pragma unroll
        for (int g = 0; g < 4; g++) {
            uint32_t off = (b_row + g * 16) * 128 + (b_chk + ks * 2) * 16;
            uint32_t r[4];
            LDSM4(r, bbase + swz(off));
            bf[buf][2 * g][0] = r[0];     bf[buf][2 * g][1] = r[1];
            bf[buf][2 * g + 1][0] = r[2]; bf[buf][2 * g + 1][1] = r[3];
        }
    };
    auto mma_block = [&](int buf) {
#pragma unroll
        for (int t = 0; t < 4; t++)
#pragma unroll
            for (int n = 0; n < 8; n++)
                MMA16816(acc[t][n], af[buf][t], bf[buf][n]);
    };

    // Wait stage 0 (leave stage 1 in flight), prefetch its ks=0 fragments.
    CP_WAIT(1);
    __syncthreads();
    load_frag(0, sb + 0 * STAGE, 0);

    for (int kt = 0; kt < KT; kt++) {
        const uint32_t abase = sb + (kt % S) * STAGE;
        // Barrier: about to overwrite slot (kt+2)%S == (kt-1)%S. All reads of
        // stage kt-1 (and the prefetch read of stage kt) happened before here.
        __syncthreads();

        load_frag(1, abase, 1);          // ks=1 frags first (critical path)
        mma_block(0);                    // ks=0 (prefetched)

        if (kt + 2 < KT) {               // issue next stage UNCOMMITTED
            loadA(kt + 2, (kt + 2) % S);
            loadB(kt + 2, (kt + 2) % S);
        }

        load_frag(0, abase, 2);
        mma_block(1);                    // ks=1

        load_frag(1, abase, 3);
        mma_block(0);                    // ks=2

        if (kt + 1 < KT) {
            CP_WAIT(0);                  // drains stage kt+1 only (kt+2 uncommitted)
            load_frag(0, sb + ((kt + 1) % S) * STAGE, 0);   // prefetch next ks=0
        }
        mma_block(1);                    // ks=3
        CP_COMMIT();                     // name stage kt+2's group
    }

    // Epilogue: direct float2 stores
#pragma unroll
    for (int t = 0; t < 4; t++) {
        const int r0 = m0 + wm * 64 + t * 16 + gid;
        float* y0 = Y + (size_t)r0 * D_OUT + n0 + wn * 64 + tig * 2;
        float* y1 = y0 + (size_t)8 * D_OUT;
#pragma unroll
        for (int n = 0; n < 8; n++) {
            *(float2*)(y0 + n * 8) = make_float2(acc[t][n][0], acc[t][n][1]);
            *(float2*)(y1 + n * 8) = make_float2(acc[t][n][2], acc[t][n][3]);
        }
    }
}

// ------------------------------- launcher ----------------------------------
extern "C" void kernel_launch(void* const* d_in, const int* in_sizes, int n_in,
                              void* d_out, int out_size) {
    const float* X  = (const float*)d_in[0];
    const float* Wq = (const float*)d_in[1];
    const float* c1 = (const float*)d_in[2];
    const float* ck = (const float*)d_in[3];
    const float* L1 = (const float*)d_in[4];
    const float* L2 = (const float*)d_in[5];
    float* Y = (float*)d_out;

    cudaFuncSetAttribute(gemm_kernel, cudaFuncAttributeMaxDynamicSharedMemorySize, SMEM_SZ);

    pack_x_kernel<<<(NROWS * D_IN / 4) / 256, 256>>>(X);
    pack_w_kernel<<<dim3(D_OUT / 64, D_IN / 64), 256>>>(Wq, c1, ck, L1, L2);
    gemm_kernel<<<dim3(D_OUT / BN, NROWS / BM), 128, SMEM_SZ>>>(Y);
}

// round 12
// speedup vs baseline: 1.0470x; 1.0241x over previous
#include <cuda_runtime.h>
#include <cuda_fp16.h>
#include <cstdint>

// Y = X @ (W_nf4 * c1 * c_kbit_2) + (X@L1)@L2  ==  X @ W'  with
//   W' = W_nf4*c1*c_kbit_2 + L1@L2   (rank-16 update folded into the weight)
// R11->R12: single change KPAD 4128 -> 4160. The 8320B row stride (65 x 128B)
// is the empirically-proven L2-slice-friendly stride from R3-R8 (GEMM 536.8us
// over 65 tiles); 4128's 8256B stride left ~25us on the table. Pad columns
// (4096..4159) are never read or written.
//   Xe fp16 [8192,4160] (cols 0..4095 = fp16(X))
//   We fp16 [4096,4160] (cols 0..4095 = fp16(W^T + (L1@L2)^T))
// GEMM via mma.sync.m16n8k16 (tcgen05 rejected at plain sm_103 PTX target);
// proven R6/R8 cross-iteration-prefetch pipeline, KT=64.

static constexpr int D_IN  = 4096;
static constexpr int D_OUT = 4096;
static constexpr int NROWS = 8192;
static constexpr int KPAD  = 4160;    // 8320B stride = 65 x 128B (proven)

static constexpr int BM = 128, BN = 128, BK = 64, S = 3;
static constexpr int KT = D_IN / BK;              // 64
static constexpr int ABYTES = BM * BK * 2;        // 16384
static constexpr int BBYTES = BN * BK * 2;        // 16384
static constexpr int STAGE  = ABYTES + BBYTES;    // 32768
static constexpr int SMEM_SZ = S * STAGE;         // 98304 (2 CTAs/SM)

__device__ __align__(16) __half g_Xe[(size_t)NROWS * KPAD];   // 68 MB
__device__ __align__(16) __half g_We[(size_t)D_OUT * KPAD];   // 34 MB

// ------------------------------ PTX helpers -------------------------------
__device__ __forceinline__ void cp16(uint32_t dst, const void* src) {
    asm volatile("cp.async.cg.shared.global [%0], [%1], 16;"
                 :: "r"(dst), "l"(__cvta_generic_to_global(src)) : "memory");
}
#define CP_COMMIT() asm volatile("cp.async.commit_group;" ::: "memory")
#define CP_WAIT(n)  asm volatile("cp.async.wait_group %0;" :: "n"(n) : "memory")

#define LDSM4(r, a) \
    asm volatile("ldmatrix.sync.aligned.m8n8.x4.shared.b16 {%0,%1,%2,%3}, [%4];" \
        : "=r"((r)[0]), "=r"((r)[1]), "=r"((r)[2]), "=r"((r)[3]) : "r"(a))

#define MMA16816(d, a, b) \
    asm volatile("mma.sync.aligned.m16n8k16.row.col.f32.f16.f16.f32 " \
        "{%0,%1,%2,%3}, {%4,%5,%6,%7}, {%8,%9}, {%0,%1,%2,%3};" \
        : "+f"((d)[0]), "+f"((d)[1]), "+f"((d)[2]), "+f"((d)[3]) \
        : "r"((a)[0]), "r"((a)[1]), "r"((a)[2]), "r"((a)[3]), \
          "r"((b)[0]), "r"((b)[1]))

__device__ __forceinline__ uint32_t swz(uint32_t o) { return o ^ ((o >> 3) & 0x70); }

// ------------------- pack_X: fp32 -> fp16 convert (padded rows) ------------
__global__ void __launch_bounds__(256)
pack_x_kernel(const float* __restrict__ X) {
    size_t e = ((size_t)blockIdx.x * 256 + threadIdx.x) * 4;   // index into X
    size_t row = e >> 12, col = e & 4095;
    float4 v = *(const float4*)(X + e);
    __half* dst = g_Xe + row * KPAD + col;
    *(__half2*)(dst)     = __floats2half2_rn(v.x, v.y);
    *(__half2*)(dst + 2) = __floats2half2_rn(v.z, v.w);
}

// -------- pack_W: dequant + rank-16 LoRA add + transpose to We -------------
__global__ void __launch_bounds__(256)
pack_w_kernel(const float* __restrict__ Wq, const float* __restrict__ c1p,
              const float* __restrict__ ck, const float* __restrict__ L1,
              const float* __restrict__ L2) {
    __shared__ float tile[64 * 65];      // dequantized W tile (k-major)
    __shared__ float sL2[16][68];        // L2[j][n0+n]
    const float c1 = *c1p;
    const int tid = threadIdx.x;
    const int n0 = blockIdx.x * 64, k0 = blockIdx.y * 64;
    const int cidx = tid & 63, ridx = tid >> 6;

#pragma unroll
    for (int ro = 0; ro < 16; ro++) {
        int kk = ro * 4 + ridx;
        size_t g = (size_t)(k0 + kk) * D_OUT + n0 + cidx;
        tile[kk * 65 + cidx] = Wq[g] * c1 * ck[g];
    }

    {   // L2 tile: 16 rows x 64 cols, 4 per thread
        int i = tid * 4;
        int j = i >> 6, c = i & 63;
        float4 v = *(const float4*)(L2 + (size_t)j * D_OUT + n0 + c);
        sL2[j][c] = v.x; sL2[j][c + 1] = v.y;
        sL2[j][c + 2] = v.z; sL2[j][c + 3] = v.w;
    }

    float l1r[16];                       // L1 row for k = k0 + cidx
    {
        const float4* lp = (const float4*)(L1 + (size_t)(k0 + cidx) * 16);
#pragma unroll
        for (int q = 0; q < 4; q++) {
            float4 v = lp[q];
            l1r[q * 4] = v.x; l1r[q * 4 + 1] = v.y;
            l1r[q * 4 + 2] = v.z; l1r[q * 4 + 3] = v.w;
        }
    }
    __syncthreads();

#pragma unroll
    for (int ro = 0; ro < 16; ro++) {
        int nn = ro * 4 + ridx;          // same nn across each warp -> broadcast
        float acc = tile[cidx * 65 + nn];
#pragma unroll
        for (int j = 0; j < 16; j++)
            acc += l1r[j] * sL2[j][nn];
        g_We[(size_t)(n0 + nn) * KPAD + k0 + cidx] = __float2half_rn(acc);
    }
}

// ------------------------------ GEMM kernel --------------------------------
// Exact R6/R8 loop: 4 warps (2x2), warp tile 64x64, cross-iteration frag
// prefetch with deferred commit_group; sync -> load_frag(1) -> mma(0).
__global__ void __launch_bounds__(128, 2)
gemm_kernel(float* __restrict__ Y) {
    extern __shared__ char smem[];
    const uint32_t sb = (uint32_t)__cvta_generic_to_shared(smem);
    const int tid = threadIdx.x, wid = tid >> 5, lane = tid & 31;
    const int m0 = blockIdx.y * BM, n0 = blockIdx.x * BN;
    const int wm = wid & 1, wn = wid >> 1;
    const int gid = lane >> 2, tig = lane & 3;

    auto loadA = [&](int kt, int slot) {
        const __half* src = g_Xe + (size_t)m0 * KPAD + (size_t)kt * BK;
        uint32_t base = sb + slot * STAGE;
#pragma unroll
        for (int i = 0; i < 8; i++) {
            int idx = tid + i * 128;
            int r = idx >> 3, c = idx & 7;
            cp16(base + swz((uint32_t)(r * 128 + c * 16)),
                 src + (size_t)r * KPAD + c * 8);
        }
    };
    auto loadB = [&](int kt, int slot) {
        const __half* src = g_We + (size_t)n0 * KPAD + (size_t)kt * BK;
        uint32_t base = sb + slot * STAGE + ABYTES;
#pragma unroll
        for (int i = 0; i < 8; i++) {
            int idx = tid + i * 128;
            int r = idx >> 3, c = idx & 7;
            cp16(base + swz((uint32_t)(r * 128 + c * 16)),
                 src + (size_t)r * KPAD + c * 8);
        }
    };

    float acc[4][8][4];
#pragma unroll
    for (int t = 0; t < 4; t++)
#pragma unroll
        for (int n = 0; n < 8; n++)
#pragma unroll
            for (int j = 0; j < 4; j++) acc[t][n][j] = 0.f;

#pragma unroll
    for (int s = 0; s < S - 1; s++) { loadA(s, s); loadB(s, s); CP_COMMIT(); }

    const uint32_t a_row = (uint32_t)(wm * 64 + (lane & 15));
    const uint32_t a_chk = (uint32_t)(lane >> 4);
    const uint32_t b_row = (uint32_t)(wn * 64 + ((lane >> 4) & 1) * 8 + (lane & 7));
    const uint32_t b_chk = (uint32_t)((lane >> 3) & 1);

    uint32_t af[2][4][4];
    uint32_t bf[2][8][2];

    auto load_frag = [&](int buf, uint32_t abase, int ks) {
        const uint32_t bbase = abase + ABYTES;
#pragma unroll
        for (int t = 0; t < 4; t++) {
            uint32_t off = (a_row + t * 16) * 128 + (a_chk + ks * 2) * 16;
            LDSM4(af[buf][t], abase + swz(off));
        }
#pragma unroll
        for (int g = 0; g < 4; g++) {
            uint32_t off = (b_row + g * 16) * 128 + (b_chk + ks * 2) * 16;
            uint32_t r[4];
            LDSM4(r, bbase + swz(off));
            bf[buf][2 * g][0] = r[0];     bf[buf][2 * g][1] = r[1];
            bf[buf][2 * g + 1][0] = r[2]; bf[buf][2 * g + 1][1] = r[3];
        }
    };
    auto mma_block = [&](int buf) {
#pragma unroll
        for (int t = 0; t < 4; t++)
#pragma unroll
            for (int n = 0; n < 8; n++)
                MMA16816(acc[t][n], af[buf][t], bf[buf][n]);
    };

    // Wait stage 0 (leave stage 1 in flight), prefetch its ks=0 fragments.
    CP_WAIT(1);
    __syncthreads();
    load_frag(0, sb + 0 * STAGE, 0);

    for (int kt = 0; kt < KT; kt++) {
        const uint32_t abase = sb + (kt % S) * STAGE;
        // Barrier: about to overwrite slot (kt+2)%S == (kt-1)%S. All reads of
        // stage kt-1 (and the prefetch read of stage kt) happened before here.
        __syncthreads();

        load_frag(1, abase, 1);          // ks=1 frags first (critical path)
        mma_block(0);                    // ks=0 (prefetched)

        if (kt + 2 < KT) {               // issue next stage UNCOMMITTED
            loadA(kt + 2, (kt + 2) % S);
            loadB(kt + 2, (kt + 2) % S);
        }

        load_frag(0, abase, 2);
        mma_block(1);                    // ks=1

        load_frag(1, abase, 3);
        mma_block(0);                    // ks=2

        if (kt + 1 < KT) {
            CP_WAIT(0);                  // drains stage kt+1 only (kt+2 uncommitted)
            load_frag(0, sb + ((kt + 1) % S) * STAGE, 0);   // prefetch next ks=0
        }
        mma_block(1);                    // ks=3
        CP_COMMIT();                     // name stage kt+2's group
    }

    // Epilogue: direct float2 stores
#pragma unroll
    for (int t = 0; t < 4; t++) {
        const int r0 = m0 + wm * 64 + t * 16 + gid;
        float* y0 = Y + (size_t)r0 * D_OUT + n0 + wn * 64 + tig * 2;
        float* y1 = y0 + (size_t)8 * D_OUT;
#pragma unroll
        for (int n = 0; n < 8; n++) {
            *(float2*)(y0 + n * 8) = make_float2(acc[t][n][0], acc[t][n][1]);
            *(float2*)(y1 + n * 8) = make_float2(acc[t][n][2], acc[t][n][3]);
        }
    }
}

// ------------------------------- launcher ----------------------------------
extern "C" void kernel_launch(void* const* d_in, const int* in_sizes, int n_in,
                              void* d_out, int out_size) {
    const float* X  = (const float*)d_in[0];
    const float* Wq = (const float*)d_in[1];
    const float* c1 = (const float*)d_in[2];
    const float* ck = (const float*)d_in[3];
    const float* L1 = (const float*)d_in[4];
    const float* L2 = (const float*)d_in[5];
    float* Y = (float*)d_out;

    cudaFuncSetAttribute(gemm_kernel, cudaFuncAttributeMaxDynamicSharedMemorySize, SMEM_SZ);

    pack_x_kernel<<<(NROWS * D_IN / 4) / 256, 256>>>(X);
    pack_w_kernel<<<dim3(D_OUT / 64, D_IN / 64), 256>>>(Wq, c1, ck, L1, L2);
    gemm_kernel<<<dim3(D_OUT / BN, NROWS / BM), 128, SMEM_SZ>>>(Y);
}

// round 14
// speedup vs baseline: 1.0729x; 1.0247x over previous
#include <cuda_runtime.h>
#include <cuda_fp16.h>
#include <cstdint>

// Y = X @ (W_nf4 * c1 * c_kbit_2) + (X@L1)@L2  ==  X @ W'  with
//   W' = W_nf4*c1*c_kbit_2 + L1@L2   (rank-16 update folded into the weight)
// R13->R14: compile fix only (__half2_as_uint doesn't exist; use pointer bit
// copy). pack_w rework as R13: 4x4 register sub-blocks (outer-product LoRA),
// float4 global loads, uint2 coalesced stores. pack_x + GEMM byte-identical
// to R12 (KPAD=4160 proven stride, R6/R8 GEMM pipeline, KT=64).
//   Xe fp16 [8192,4160] (cols 0..4095 = fp16(X))
//   We fp16 [4096,4160] (cols 0..4095 = fp16(W^T + (L1@L2)^T))

static constexpr int D_IN  = 4096;
static constexpr int D_OUT = 4096;
static constexpr int NROWS = 8192;
static constexpr int KPAD  = 4160;    // 8320B stride = 65 x 128B (proven)

static constexpr int BM = 128, BN = 128, BK = 64, S = 3;
static constexpr int KT = D_IN / BK;              // 64
static constexpr int ABYTES = BM * BK * 2;        // 16384
static constexpr int BBYTES = BN * BK * 2;        // 16384
static constexpr int STAGE  = ABYTES + BBYTES;    // 32768
static constexpr int SMEM_SZ = S * STAGE;         // 98304 (2 CTAs/SM)

__device__ __align__(16) __half g_Xe[(size_t)NROWS * KPAD];   // 68 MB
__device__ __align__(16) __half g_We[(size_t)D_OUT * KPAD];   // 34 MB

// ------------------------------ PTX helpers -------------------------------
__device__ __forceinline__ void cp16(uint32_t dst, const void* src) {
    asm volatile("cp.async.cg.shared.global [%0], [%1], 16;"
                 :: "r"(dst), "l"(__cvta_generic_to_global(src)) : "memory");
}
#define CP_COMMIT() asm volatile("cp.async.commit_group;" ::: "memory")
#define CP_WAIT(n)  asm volatile("cp.async.wait_group %0;" :: "n"(n) : "memory")

#define LDSM4(r, a) \
    asm volatile("ldmatrix.sync.aligned.m8n8.x4.shared.b16 {%0,%1,%2,%3}, [%4];" \
        : "=r"((r)[0]), "=r"((r)[1]), "=r"((r)[2]), "=r"((r)[3]) : "r"(a))

#define MMA16816(d, a, b) \
    asm volatile("mma.sync.aligned.m16n8k16.row.col.f32.f16.f16.f32 " \
        "{%0,%1,%2,%3}, {%4,%5,%6,%7}, {%8,%9}, {%0,%1,%2,%3};" \
        : "+f"((d)[0]), "+f"((d)[1]), "+f"((d)[2]), "+f"((d)[3]) \
        : "r"((a)[0]), "r"((a)[1]), "r"((a)[2]), "r"((a)[3]), \
          "r"((b)[0]), "r"((b)[1]))

__device__ __forceinline__ uint32_t swz(uint32_t o) { return o ^ ((o >> 3) & 0x70); }

// ------------------- pack_X: fp32 -> fp16 convert (padded rows) ------------
__global__ void __launch_bounds__(256)
pack_x_kernel(const float* __restrict__ X) {
    size_t e = ((size_t)blockIdx.x * 256 + threadIdx.x) * 4;   // index into X
    size_t row = e >> 12, col = e & 4095;
    float4 v = *(const float4*)(X + e);
    __half* dst = g_Xe + row * KPAD + col;
    *(__half2*)(dst)     = __floats2half2_rn(v.x, v.y);
    *(__half2*)(dst + 2) = __floats2half2_rn(v.z, v.w);
}

// -------- pack_W: dequant + rank-16 LoRA add + transpose to We -------------
// 64x64 tile per block. Phase 1: float4 dequant into smem tile[k][n] (+L1/L2
// tiles). Phase 2: each thread owns a 4k x 4n sub-block: outer-product LoRA
// accumulation (per j: 4+4 LDS feed 16 FMA), then uint2 stores of 4
// k-contiguous halfs => 128B-coalesced We writes.
__global__ void __launch_bounds__(256)
pack_w_kernel(const float* __restrict__ Wq, const float* __restrict__ c1p,
              const float* __restrict__ ck, const float* __restrict__ L1,
              const float* __restrict__ L2) {
    __shared__ float tile[64 * 65];      // dequantized W tile, tile[k*65+n]
    __shared__ float sL1[64 * 17];       // L1[k0+k][j]  at sL1[k*17+j]
    __shared__ float sL2[16 * 68];       // L2[j][n0+n] at sL2[j*68+n]
    const float c1 = *c1p;
    const int tid = threadIdx.x;
    const int n0 = blockIdx.x * 64, k0 = blockIdx.y * 64;

    // Phase 1: dequant 64x64 via float4 (4 rows x 16 n-groups per iter)
    {
        const int tq = tid & 15, tr = tid >> 4;
#pragma unroll
        for (int i = 0; i < 4; i++) {
            int kk = tr + 16 * i;
            int nc = tq * 4;
            size_t g = (size_t)(k0 + kk) * D_OUT + n0 + nc;
            float4 w = *(const float4*)(Wq + g);
            float4 s = *(const float4*)(ck + g);
            float* tp = tile + kk * 65 + nc;
            tp[0] = w.x * c1 * s.x;
            tp[1] = w.y * c1 * s.y;
            tp[2] = w.z * c1 * s.z;
            tp[3] = w.w * c1 * s.w;
        }
        // sL1: 64 rows x 16 (one float4 per thread)
        int kr = tid >> 2, j4 = (tid & 3) * 4;
        float4 v1 = *(const float4*)(L1 + (size_t)(k0 + kr) * 16 + j4);
        float* lp = sL1 + kr * 17 + j4;
        lp[0] = v1.x; lp[1] = v1.y; lp[2] = v1.z; lp[3] = v1.w;
        // sL2: 16 rows x 64 (one float4 per thread; 68-pad keeps 16B align)
        int jj = tid >> 4, c = (tid & 15) * 4;
        float4 v2 = *(const float4*)(L2 + (size_t)jj * D_OUT + n0 + c);
        *(float4*)(sL2 + jj * 68 + c) = v2;
    }
    __syncthreads();

    // Phase 2: 4k x 4n sub-block per thread
    const int k4 = (tid & 15) * 4;       // k base (lane-contiguous for stores)
    const int n4 = (tid >> 4) * 4;       // n base
    float acc[4][4];
#pragma unroll
    for (int i = 0; i < 4; i++)
#pragma unroll
        for (int q = 0; q < 4; q++)
            acc[i][q] = tile[(k4 + i) * 65 + n4 + q];

#pragma unroll
    for (int j = 0; j < 16; j++) {
        float l2q[4], l1i[4];
#pragma unroll
        for (int q = 0; q < 4; q++) l2q[q] = sL2[j * 68 + n4 + q];
#pragma unroll
        for (int i = 0; i < 4; i++) l1i[i] = sL1[(k4 + i) * 17 + j];
#pragma unroll
        for (int i = 0; i < 4; i++)
#pragma unroll
            for (int q = 0; q < 4; q++)
                acc[i][q] += l1i[i] * l2q[q];
    }

#pragma unroll
    for (int q = 0; q < 4; q++) {
        __half2 h0 = __floats2half2_rn(acc[0][q], acc[1][q]);
        __half2 h1 = __floats2half2_rn(acc[2][q], acc[3][q]);
        uint2 u;
        u.x = *(uint32_t*)&h0;
        u.y = *(uint32_t*)&h1;
        *(uint2*)(g_We + (size_t)(n0 + n4 + q) * KPAD + k0 + k4) = u;
    }
}

// ------------------------------ GEMM kernel --------------------------------
// Exact R6/R8 loop: 4 warps (2x2), warp tile 64x64, cross-iteration frag
// prefetch with deferred commit_group; sync -> load_frag(1) -> mma(0).
__global__ void __launch_bounds__(128, 2)
gemm_kernel(float* __restrict__ Y) {
    extern __shared__ char smem[];
    const uint32_t sb = (uint32_t)__cvta_generic_to_shared(smem);
    const int tid = threadIdx.x, wid = tid >> 5, lane = tid & 31;
    const int m0 = blockIdx.y * BM, n0 = blockIdx.x * BN;
    const int wm = wid & 1, wn = wid >> 1;
    const int gid = lane >> 2, tig = lane & 3;

    auto loadA = [&](int kt, int slot) {
        const __half* src = g_Xe + (size_t)m0 * KPAD + (size_t)kt * BK;
        uint32_t base = sb + slot * STAGE;
#pragma unroll
        for (int i = 0; i < 8; i++) {
            int idx = tid + i * 128;
            int r = idx >> 3, c = idx & 7;
            cp16(base + swz((uint32_t)(r * 128 + c * 16)),
                 src + (size_t)r * KPAD + c * 8);
        }
    };
    auto loadB = [&](int kt, int slot) {
        const __half* src = g_We + (size_t)n0 * KPAD + (size_t)kt * BK;
        uint32_t base = sb + slot * STAGE + ABYTES;
#pragma unroll
        for (int i = 0; i < 8; i++) {
            int idx = tid + i * 128;
            int r = idx >> 3, c = idx & 7;
            cp16(base + swz((uint32_t)(r * 128 + c * 16)),
                 src + (size_t)r * KPAD + c * 8);
        }
    };

    float acc[4][8][4];
#pragma unroll
    for (int t = 0; t < 4; t++)
#pragma unroll
        for (int n = 0; n < 8; n++)
#pragma unroll
            for (int j = 0; j < 4; j++) acc[t][n][j] = 0.f;

#pragma unroll
    for (int s = 0; s < S - 1; s++) { loadA(s, s); loadB(s, s); CP_COMMIT(); }

    const uint32_t a_row = (uint32_t)(wm * 64 + (lane & 15));
    const uint32_t a_chk = (uint32_t)(lane >> 4);
    const uint32_t b_row = (uint32_t)(wn * 64 + ((lane >> 4) & 1) * 8 + (lane & 7));
    const uint32_t b_chk = (uint32_t)((lane >> 3) & 1);

    uint32_t af[2][4][4];
    uint32_t bf[2][8][2];

    auto load_frag = [&](int buf, uint32_t abase, int ks) {
        const uint32_t bbase = abase + ABYTES;
#pragma unroll
        for (int t = 0; t < 4; t++) {
            uint32_t off = (a_row + t * 16) * 128 + (a_chk + ks * 2) * 16;
            LDSM4(af[buf][t], abase + swz(off));
        }
#pragma unroll
        for (int g = 0; g < 4; g++) {
            uint32_t off = (b_row + g * 16) * 128 + (b_chk + ks * 2) * 16;
            uint32_t r[4];
            LDSM4(r, bbase + swz(off));
            bf[buf][2 * g][0] = r[0];     bf[buf][2 * g][1] = r[1];
            bf[buf][2 * g + 1][0] = r[2]; bf[buf][2 * g + 1][1] = r[3];
        }
    };
    auto mma_block = [&](int buf) {
#pragma unroll
        for (int t = 0; t < 4; t++)
#pragma unroll
            for (int n = 0; n < 8; n++)
                MMA16816(acc[t][n], af[buf][t], bf[buf][n]);
    };

    // Wait stage 0 (leave stage 1 in flight), prefetch its ks=0 fragments.
    CP_WAIT(1);
    __syncthreads();
    load_frag(0, sb + 0 * STAGE, 0);

    for (int kt = 0; kt < KT; kt++) {
        const uint32_t abase = sb + (kt % S) * STAGE;
        // Barrier: about to overwrite slot (kt+2)%S == (kt-1)%S. All reads of
        // stage kt-1 (and the prefetch read of stage kt) happened before here.
        __syncthreads();

        load_frag(1, abase, 1);          // ks=1 frags first (critical path)
        mma_block(0);                    // ks=0 (prefetched)

        if (kt + 2 < KT) {               // issue next stage UNCOMMITTED
            loadA(kt + 2, (kt + 2) % S);
            loadB(kt + 2, (kt + 2) % S);
        }

        load_frag(0, abase, 2);
        mma_block(1);                    // ks=1

        load_frag(1, abase, 3);
        mma_block(0);                    // ks=2

        if (kt + 1 < KT) {
            CP_WAIT(0);                  // drains stage kt+1 only (kt+2 uncommitted)
            load_frag(0, sb + ((kt + 1) % S) * STAGE, 0);   // prefetch next ks=0
        }
        mma_block(1);                    // ks=3
        CP_COMMIT();                     // name stage kt+2's group
    }

    // Epilogue: direct float2 stores
#pragma unroll
    for (int t = 0; t < 4; t++) {
        const int r0 = m0 + wm * 64 + t * 16 + gid;
        float* y0 = Y + (size_t)r0 * D_OUT + n0 + wn * 64 + tig * 2;
        float* y1 = y0 + (size_t)8 * D_OUT;
#pragma unroll
        for (int n = 0; n < 8; n++) {
            *(float2*)(y0 + n * 8) = make_float2(acc[t][n][0], acc[t][n][1]);
            *(float2*)(y1 + n * 8) = make_float2(acc[t][n][2], acc[t][n][3]);
        }
    }
}

// ------------------------------- launcher ----------------------------------
extern "C" void kernel_launch(void* const* d_in, const int* in_sizes, int n_in,
                              void* d_out, int out_size) {
    const float* X  = (const float*)d_in[0];
    const float* Wq = (const float*)d_in[1];
    const float* c1 = (const float*)d_in[2];
    const float* ck = (const float*)d_in[3];
    const float* L1 = (const float*)d_in[4];
    const float* L2 = (const float*)d_in[5];
    float* Y = (float*)d_out;

    cudaFuncSetAttribute(gemm_kernel, cudaFuncAttributeMaxDynamicSharedMemorySize, SMEM_SZ);

    pack_x_kernel<<<(NROWS * D_IN / 4) / 256, 256>>>(X);
    pack_w_kernel<<<dim3(D_OUT / 64, D_IN / 64), 256>>>(Wq, c1, ck, L1, L2);
    gemm_kernel<<<dim3(D_OUT / BN, NROWS / BM), 128, SMEM_SZ>>>(Y);
}